// round 4
// baseline (speedup 1.0000x reference)
#include <cuda_runtime.h>
#include <cuda_bf16.h>
#include <cstdint>

// ===========================================================================
// TrainableMPOLayer: y = X @ W^T + bias, W = dense collapse of 3-core MPO.
//   1) T01 = core0 x core1
//   2) Whi/Wlo bf16 = split(T01 x core2)     [smem-tiled batched GEMM]
//   3) Xhi/Xlo bf16 = split(x)
//   4) Y = Xhi*Whi + Xhi*Wlo + Xlo*Whi + bias  via mma.sync bf16 (HMMA),
//      BK=32, 80B-padded rows (conflict-free ldmatrix), 2 CTAs/SM.
// ===========================================================================

#define KDIM 4096
#define MDIM 1024
#define NDIM 4096

__device__ float          g_T01[256 * 256 * 32];        // 8 MB
__device__ __nv_bfloat16  g_Whi[(size_t)4096 * 4096];   // 32 MB
__device__ __nv_bfloat16  g_Wlo[(size_t)4096 * 4096];   // 32 MB
__device__ __nv_bfloat16  g_Xhi[(size_t)1024 * 4096];   // 8 MB
__device__ __nv_bfloat16  g_Xlo[(size_t)1024 * 4096];   // 8 MB

// ---------------------------------------------------------------------------
// helpers
// ---------------------------------------------------------------------------
__device__ __forceinline__ uint32_t smem_u32(const void* p) {
    uint32_t a;
    asm("{ .reg .u64 t; cvta.to.shared.u64 t, %1; cvt.u32.u64 %0, t; }"
        : "=r"(a) : "l"(p));
    return a;
}

__device__ __forceinline__ void cpasync16(uint32_t dst, const void* src) {
    asm volatile("cp.async.cg.shared.global [%0], [%1], 16;"
                 :: "r"(dst), "l"(src) : "memory");
}

__device__ __forceinline__ void ldsm4(uint32_t& r0, uint32_t& r1,
                                      uint32_t& r2, uint32_t& r3, uint32_t a) {
    asm volatile("ldmatrix.sync.aligned.m8n8.x4.shared.b16 {%0,%1,%2,%3}, [%4];"
                 : "=r"(r0), "=r"(r1), "=r"(r2), "=r"(r3) : "r"(a));
}

__device__ __forceinline__ void mma16816(float* d, const uint32_t* a,
                                         uint32_t b0, uint32_t b1) {
    asm volatile(
        "mma.sync.aligned.m16n8k16.row.col.f32.bf16.bf16.f32 "
        "{%0,%1,%2,%3}, {%4,%5,%6,%7}, {%8,%9}, {%0,%1,%2,%3};"
        : "+f"(d[0]), "+f"(d[1]), "+f"(d[2]), "+f"(d[3])
        : "r"(a[0]), "r"(a[1]), "r"(a[2]), "r"(a[3]), "r"(b0), "r"(b1));
}

// ---------------------------------------------------------------------------
// Kernel 1: T01[ii, jj, r2] = sum_r1 core0[i1,j1,r1] * core1[r1,i2,j2,r2]
// ---------------------------------------------------------------------------
__global__ void build_t01_kernel(const float* __restrict__ c0,
                                 const float* __restrict__ c1) {
    int idx = blockIdx.x * blockDim.x + threadIdx.x;   // 0 .. 256*256*8-1
    int r2q = idx & 7;
    int jj  = (idx >> 3) & 255;
    int ii  = idx >> 11;
    int j1 = jj >> 4, j2 = jj & 15;
    int i1 = ii >> 4, i2 = ii & 15;

    const float*  a = c0 + (i1 * 16 + j1) * 32;
    const float4* b = (const float4*)(c1 + i2 * 512 + j2 * 32 + r2q * 4);

    float4 s = make_float4(0.f, 0.f, 0.f, 0.f);
#pragma unroll
    for (int r1 = 0; r1 < 32; ++r1) {
        float  av = a[r1];
        float4 bv = b[(size_t)r1 * 2048];
        s.x += av * bv.x; s.y += av * bv.y; s.z += av * bv.z; s.w += av * bv.w;
    }
    *(float4*)(g_T01 + (size_t)idx * 4) = s;
}

// ---------------------------------------------------------------------------
// Kernel 2 (rewritten): per block: one ii (16 W-rows), 64 jj (1024 W-cols).
// smem: c2s[32][256] (32KB) + T01t[32][68pad] (8.7KB, transposed over jj).
// Thread (jjg = tid>>4, i3 = tid&15): acc[4 jj][16 j3], 32 r2 iterations.
// W[ii*16+i3, (jjb+jj)*16+j3] = sum_r2 T01[ii,jjb+jj,r2] * c2[r2,i3,j3]
// ---------------------------------------------------------------------------
#define T01T_PITCH 68   // floats; 272B (16B aligned), bank stride 4 -> 4-way max

__global__ __launch_bounds__(256)
void build_w_kernel(const float* __restrict__ c2) {
    __shared__ __align__(16) float c2s[32 * 256];
    __shared__ __align__(16) float t01t[32 * T01T_PITCH];

    const int tid = threadIdx.x;
    const int ii  = blockIdx.y;          // 0..255
    const int jjb = blockIdx.x * 64;     // 0,64,128,192

    // stage c2 (8192 floats)
#pragma unroll
    for (int c = tid; c < 2048; c += 256)
        *(float4*)&c2s[c * 4] = *(const float4*)&c2[c * 4];
    // stage + transpose T01 rows [jjb..jjb+63]
#pragma unroll
    for (int c = tid; c < 2048; c += 256) {
        int jj = c >> 5, r2 = c & 31;
        t01t[r2 * T01T_PITCH + jj] = g_T01[((size_t)ii * 256 + jjb + jj) * 32 + r2];
    }
    __syncthreads();

    const int jjg = tid >> 4;            // 0..15 -> jj = jjg*4..+3
    const int i3  = tid & 15;

    float acc[4][16];
#pragma unroll
    for (int a = 0; a < 4; ++a)
#pragma unroll
        for (int b = 0; b < 16; ++b) acc[a][b] = 0.f;

#pragma unroll
    for (int r2 = 0; r2 < 32; ++r2) {
        float4 tv = *(const float4*)&t01t[r2 * T01T_PITCH + jjg * 4];
        const float* crow = &c2s[r2 * 256 + i3 * 16];
        float4 cv0 = *(const float4*)&crow[0];
        float4 cv1 = *(const float4*)&crow[4];
        float4 cv2 = *(const float4*)&crow[8];
        float4 cv3 = *(const float4*)&crow[12];
        float cva[16] = {cv0.x, cv0.y, cv0.z, cv0.w, cv1.x, cv1.y, cv1.z, cv1.w,
                         cv2.x, cv2.y, cv2.z, cv2.w, cv3.x, cv3.y, cv3.z, cv3.w};
        float tva[4] = {tv.x, tv.y, tv.z, tv.w};
#pragma unroll
        for (int a = 0; a < 4; ++a)
#pragma unroll
            for (int b = 0; b < 16; ++b)
                acc[a][b] += tva[a] * cva[b];
    }

    // write hi/lo: row = ii*16+i3, cols = (jjb+jjg*4+a)*16 + b
    const size_t rowoff = (size_t)(ii * 16 + i3) * 4096;
#pragma unroll
    for (int a = 0; a < 4; ++a) {
        const size_t o = rowoff + (size_t)(jjb + jjg * 4 + a) * 16;
        __nv_bfloat162 hibuf[8], lobuf[8];
#pragma unroll
        for (int p = 0; p < 8; ++p) {
            float v0 = acc[a][2 * p], v1 = acc[a][2 * p + 1];
            __nv_bfloat16 h0 = __float2bfloat16(v0);
            __nv_bfloat16 h1 = __float2bfloat16(v1);
            hibuf[p] = __nv_bfloat162(h0, h1);
            lobuf[p] = __nv_bfloat162(__float2bfloat16(v0 - __bfloat162float(h0)),
                                      __float2bfloat16(v1 - __bfloat162float(h1)));
        }
        *(uint4*)(g_Whi + o)     = *(uint4*)&hibuf[0];
        *(uint4*)(g_Whi + o + 8) = *(uint4*)&hibuf[4];
        *(uint4*)(g_Wlo + o)     = *(uint4*)&lobuf[0];
        *(uint4*)(g_Wlo + o + 8) = *(uint4*)&lobuf[4];
    }
}

// ---------------------------------------------------------------------------
// Kernel 3: split X into bf16 hi/lo
// ---------------------------------------------------------------------------
__global__ void split_x_kernel(const float* __restrict__ x) {
    int idx = blockIdx.x * blockDim.x + threadIdx.x;
    float4 v = ((const float4*)x)[idx];
    __nv_bfloat16 h0 = __float2bfloat16(v.x);
    __nv_bfloat16 h1 = __float2bfloat16(v.y);
    __nv_bfloat16 h2 = __float2bfloat16(v.z);
    __nv_bfloat16 h3 = __float2bfloat16(v.w);
    __nv_bfloat16 l0 = __float2bfloat16(v.x - __bfloat162float(h0));
    __nv_bfloat16 l1 = __float2bfloat16(v.y - __bfloat162float(h1));
    __nv_bfloat16 l2 = __float2bfloat16(v.z - __bfloat162float(h2));
    __nv_bfloat16 l3 = __float2bfloat16(v.w - __bfloat162float(h3));
    __nv_bfloat162* Hp = (__nv_bfloat162*)g_Xhi;
    __nv_bfloat162* Lp = (__nv_bfloat162*)g_Xlo;
    Hp[idx * 2 + 0] = __nv_bfloat162(h0, h1);
    Hp[idx * 2 + 1] = __nv_bfloat162(h2, h3);
    Lp[idx * 2 + 0] = __nv_bfloat162(l0, l1);
    Lp[idx * 2 + 1] = __nv_bfloat162(l2, l3);
}

// ---------------------------------------------------------------------------
// Kernel 4: HMMA GEMM. C[1024,4096] = Xsplit @ Wsplit^T + bias
// CTA 128x128, BK=32, rows padded to 80B (ldmatrix conflict-free), 2-stage
// cp.async, 2 CTAs/SM. 8 warps = 4(M) x 2(N); warp tile 32x64.
// ---------------------------------------------------------------------------
#define GBM 128
#define GBN 128
#define GBK 32
#define NKT (KDIM / GBK)            // 128
#define ROWB 80                      // 64B data + 16B pad
#define ARR_BYTES (128 * ROWB)       // 10240
#define ST_AHI 0
#define ST_ALO (1 * ARR_BYTES)
#define ST_BHI (2 * ARR_BYTES)
#define ST_BLO (3 * ARR_BYTES)
#define STAGE_BYTES (4 * ARR_BYTES)  // 40960
#define SMEM_TOTAL (2 * STAGE_BYTES) // 81920

__device__ __forceinline__ void load_stage(uint32_t st, int bm, int bn,
                                           int kt, int tid) {
    const size_t krow = (size_t)kt * 64;      // byte offset within K row
#pragma unroll
    for (int c = tid; c < 512; c += 256) {    // 128 rows x 4 16B-chunks
        int row = c >> 2, ch = c & 3;
        uint32_t so = (uint32_t)(row * ROWB + ch * 16);
        const size_t ga = (size_t)(bm + row) * 8192 + krow + ch * 16;
        const size_t gb = (size_t)(bn + row) * 8192 + krow + ch * 16;
        cpasync16(st + ST_AHI + so, (const char*)g_Xhi + ga);
        cpasync16(st + ST_ALO + so, (const char*)g_Xlo + ga);
        cpasync16(st + ST_BHI + so, (const char*)g_Whi + gb);
        cpasync16(st + ST_BLO + so, (const char*)g_Wlo + gb);
    }
}

__global__ __launch_bounds__(256, 2)
void gemm_mma_kernel(const float* __restrict__ bias, float* __restrict__ C) {
    extern __shared__ __align__(1024) char smem[];
    const uint32_t sbase = smem_u32(smem);
    const int tid  = threadIdx.x;
    const int wid  = tid >> 5;
    const int lane = tid & 31;
    const int wm = wid & 3;          // 4 M-warps (32 rows each)
    const int wn = wid >> 2;         // 2 N-warps (64 cols each)
    const int bm = blockIdx.y * GBM;
    const int bn = blockIdx.x * GBN;

    const int lrow   = lane & 15;
    const int lchunk = (lane >> 4) * 16;

    uint32_t a_addr[2];
#pragma unroll
    for (int mt = 0; mt < 2; ++mt)
        a_addr[mt] = (uint32_t)((wm * 32 + mt * 16 + lrow) * ROWB + lchunk);
    uint32_t b_addr[4];
#pragma unroll
    for (int c = 0; c < 4; ++c)
        b_addr[c] = (uint32_t)((wn * 64 + c * 16 + lrow) * ROWB + lchunk);

    float acc[2][8][4];
#pragma unroll
    for (int mt = 0; mt < 2; ++mt)
#pragma unroll
        for (int nt = 0; nt < 8; ++nt)
#pragma unroll
            for (int e = 0; e < 4; ++e) acc[mt][nt][e] = 0.f;

    load_stage(sbase, bm, bn, 0, tid);
    asm volatile("cp.async.commit_group;" ::: "memory");

    int buf = 0;
    for (int kt = 0; kt < NKT; ++kt) {
        if (kt + 1 < NKT) {
            load_stage(sbase + (buf ^ 1) * STAGE_BYTES, bm, bn, kt + 1, tid);
            asm volatile("cp.async.commit_group;" ::: "memory");
            asm volatile("cp.async.wait_group 1;" ::: "memory");
        } else {
            asm volatile("cp.async.wait_group 0;" ::: "memory");
        }
        __syncthreads();

        const uint32_t st = sbase + buf * STAGE_BYTES;
#pragma unroll
        for (int ks = 0; ks < 2; ++ks) {
            const uint32_t kb = (uint32_t)(ks * 32);
            uint32_t ah[2][4], al[2][4];
#pragma unroll
            for (int mt = 0; mt < 2; ++mt) {
                ldsm4(ah[mt][0], ah[mt][1], ah[mt][2], ah[mt][3],
                      st + ST_AHI + a_addr[mt] + kb);
                ldsm4(al[mt][0], al[mt][1], al[mt][2], al[mt][3],
                      st + ST_ALO + a_addr[mt] + kb);
            }
#pragma unroll
            for (int c = 0; c < 4; ++c) {
                uint32_t bh[4], bl[4];
                ldsm4(bh[0], bh[1], bh[2], bh[3], st + ST_BHI + b_addr[c] + kb);
                ldsm4(bl[0], bl[1], bl[2], bl[3], st + ST_BLO + b_addr[c] + kb);
#pragma unroll
                for (int mt = 0; mt < 2; ++mt)
#pragma unroll
                    for (int o = 0; o < 2; ++o) {
                        const int nt = c * 2 + o;
                        mma16816(acc[mt][nt], ah[mt], bh[o], bh[o + 2]);
                        mma16816(acc[mt][nt], ah[mt], bl[o], bl[o + 2]);
                        mma16816(acc[mt][nt], al[mt], bh[o], bh[o + 2]);
                    }
            }
        }
        __syncthreads();
        buf ^= 1;
    }

    // epilogue
    const int gq = lane >> 2, rq = lane & 3;
#pragma unroll
    for (int mt = 0; mt < 2; ++mt) {
        const int r0 = bm + wm * 32 + mt * 16 + gq;
#pragma unroll
        for (int nt = 0; nt < 8; ++nt) {
            const int col = bn + wn * 64 + nt * 8 + rq * 2;
            float2 bv = *(const float2*)&bias[col];
            float2 o0 = make_float2(acc[mt][nt][0] + bv.x, acc[mt][nt][1] + bv.y);
            float2 o1 = make_float2(acc[mt][nt][2] + bv.x, acc[mt][nt][3] + bv.y);
            *(float2*)&C[(size_t)r0 * NDIM + col]       = o0;
            *(float2*)&C[(size_t)(r0 + 8) * NDIM + col] = o1;
        }
    }
}

// ---------------------------------------------------------------------------
extern "C" void kernel_launch(void* const* d_in, const int* in_sizes, int n_in,
                              void* d_out, int out_size) {
    const float* x     = (const float*)d_in[0];
    const float* core0 = (const float*)d_in[1];
    const float* core1 = (const float*)d_in[2];
    const float* core2 = (const float*)d_in[3];
    const float* bias  = (const float*)d_in[4];
    float* out = (float*)d_out;

    build_t01_kernel<<<(256 * 256 * 8) / 256, 256>>>(core0, core1);
    build_w_kernel<<<dim3(4, 256), 256>>>(core2);
    split_x_kernel<<<(MDIM * KDIM / 4) / 256, 256>>>(x);

    cudaFuncSetAttribute(gemm_mma_kernel,
                         cudaFuncAttributeMaxDynamicSharedMemorySize, SMEM_TOTAL);
    gemm_mma_kernel<<<dim3(NDIM / GBN, MDIM / GBM), 256, SMEM_TOTAL>>>(bias, out);
}

// round 5
// speedup vs baseline: 1.1328x; 1.1328x over previous
#include <cuda_runtime.h>
#include <cuda_bf16.h>
#include <cstdint>

// ===========================================================================
// TrainableMPOLayer: y = X @ W^T + bias, W = dense collapse of 3-core MPO.
//   1) T01 = core0 x core1
//   2) Whi/Wlo bf16 = split(T01 x core2)     [smem-tiled batched GEMM]
//   3) Xhi/Xlo bf16 = split(x)
//   4) Y = Xhi*Whi + Xhi*Wlo + Xlo*Whi + bias  via mma.sync bf16 (HMMA)
//      512 threads, 16 warps (4Mx4N, warp tile 32x32), BK=64, SW128 swizzle,
//      2-stage cp.async. ~95 regs/thread (no launch-bounds cap -> no spills).
// ===========================================================================

#define KDIM 4096
#define MDIM 1024
#define NDIM 4096

__device__ float          g_T01[256 * 256 * 32];        // 8 MB
__device__ __nv_bfloat16  g_Whi[(size_t)4096 * 4096];   // 32 MB
__device__ __nv_bfloat16  g_Wlo[(size_t)4096 * 4096];   // 32 MB
__device__ __nv_bfloat16  g_Xhi[(size_t)1024 * 4096];   // 8 MB
__device__ __nv_bfloat16  g_Xlo[(size_t)1024 * 4096];   // 8 MB

// ---------------------------------------------------------------------------
// helpers
// ---------------------------------------------------------------------------
__device__ __forceinline__ uint32_t smem_u32(const void* p) {
    uint32_t a;
    asm("{ .reg .u64 t; cvta.to.shared.u64 t, %1; cvt.u32.u64 %0, t; }"
        : "=r"(a) : "l"(p));
    return a;
}

__device__ __forceinline__ void cpasync16(uint32_t dst, const void* src) {
    asm volatile("cp.async.cg.shared.global [%0], [%1], 16;"
                 :: "r"(dst), "l"(src) : "memory");
}

__device__ __forceinline__ void ldsm4(uint32_t& r0, uint32_t& r1,
                                      uint32_t& r2, uint32_t& r3, uint32_t a) {
    asm volatile("ldmatrix.sync.aligned.m8n8.x4.shared.b16 {%0,%1,%2,%3}, [%4];"
                 : "=r"(r0), "=r"(r1), "=r"(r2), "=r"(r3) : "r"(a));
}

__device__ __forceinline__ void mma16816(float* d, const uint32_t* a,
                                         uint32_t b0, uint32_t b1) {
    asm volatile(
        "mma.sync.aligned.m16n8k16.row.col.f32.bf16.bf16.f32 "
        "{%0,%1,%2,%3}, {%4,%5,%6,%7}, {%8,%9}, {%0,%1,%2,%3};"
        : "+f"(d[0]), "+f"(d[1]), "+f"(d[2]), "+f"(d[3])
        : "r"(a[0]), "r"(a[1]), "r"(a[2]), "r"(a[3]), "r"(b0), "r"(b1));
}

// ---------------------------------------------------------------------------
// Kernel 1: T01[ii, jj, r2] = sum_r1 core0[i1,j1,r1] * core1[r1,i2,j2,r2]
// ---------------------------------------------------------------------------
__global__ void build_t01_kernel(const float* __restrict__ c0,
                                 const float* __restrict__ c1) {
    int idx = blockIdx.x * blockDim.x + threadIdx.x;   // 0 .. 256*256*8-1
    int r2q = idx & 7;
    int jj  = (idx >> 3) & 255;
    int ii  = idx >> 11;
    int j1 = jj >> 4, j2 = jj & 15;
    int i1 = ii >> 4, i2 = ii & 15;

    const float*  a = c0 + (i1 * 16 + j1) * 32;
    const float4* b = (const float4*)(c1 + i2 * 512 + j2 * 32 + r2q * 4);

    float4 s = make_float4(0.f, 0.f, 0.f, 0.f);
#pragma unroll
    for (int r1 = 0; r1 < 32; ++r1) {
        float  av = a[r1];
        float4 bv = b[(size_t)r1 * 2048];
        s.x += av * bv.x; s.y += av * bv.y; s.z += av * bv.z; s.w += av * bv.w;
    }
    *(float4*)(g_T01 + (size_t)idx * 4) = s;
}

// ---------------------------------------------------------------------------
// Kernel 2: per block: one ii (16 W-rows), 64 jj (1024 W-cols), smem-tiled.
// ---------------------------------------------------------------------------
#define T01T_PITCH 68

__global__ __launch_bounds__(256)
void build_w_kernel(const float* __restrict__ c2) {
    __shared__ __align__(16) float c2s[32 * 256];
    __shared__ __align__(16) float t01t[32 * T01T_PITCH];

    const int tid = threadIdx.x;
    const int ii  = blockIdx.y;
    const int jjb = blockIdx.x * 64;

#pragma unroll
    for (int c = tid; c < 2048; c += 256)
        *(float4*)&c2s[c * 4] = *(const float4*)&c2[c * 4];
#pragma unroll
    for (int c = tid; c < 2048; c += 256) {
        int jj = c >> 5, r2 = c & 31;
        t01t[r2 * T01T_PITCH + jj] = g_T01[((size_t)ii * 256 + jjb + jj) * 32 + r2];
    }
    __syncthreads();

    const int jjg = tid >> 4;
    const int i3  = tid & 15;

    float acc[4][16];
#pragma unroll
    for (int a = 0; a < 4; ++a)
#pragma unroll
        for (int b = 0; b < 16; ++b) acc[a][b] = 0.f;

#pragma unroll
    for (int r2 = 0; r2 < 32; ++r2) {
        float4 tv = *(const float4*)&t01t[r2 * T01T_PITCH + jjg * 4];
        const float* crow = &c2s[r2 * 256 + i3 * 16];
        float4 cv0 = *(const float4*)&crow[0];
        float4 cv1 = *(const float4*)&crow[4];
        float4 cv2 = *(const float4*)&crow[8];
        float4 cv3 = *(const float4*)&crow[12];
        float cva[16] = {cv0.x, cv0.y, cv0.z, cv0.w, cv1.x, cv1.y, cv1.z, cv1.w,
                         cv2.x, cv2.y, cv2.z, cv2.w, cv3.x, cv3.y, cv3.z, cv3.w};
        float tva[4] = {tv.x, tv.y, tv.z, tv.w};
#pragma unroll
        for (int a = 0; a < 4; ++a)
#pragma unroll
            for (int b = 0; b < 16; ++b)
                acc[a][b] += tva[a] * cva[b];
    }

    const size_t rowoff = (size_t)(ii * 16 + i3) * 4096;
#pragma unroll
    for (int a = 0; a < 4; ++a) {
        const size_t o = rowoff + (size_t)(jjb + jjg * 4 + a) * 16;
        __nv_bfloat162 hibuf[8], lobuf[8];
#pragma unroll
        for (int p = 0; p < 8; ++p) {
            float v0 = acc[a][2 * p], v1 = acc[a][2 * p + 1];
            __nv_bfloat16 h0 = __float2bfloat16(v0);
            __nv_bfloat16 h1 = __float2bfloat16(v1);
            hibuf[p] = __nv_bfloat162(h0, h1);
            lobuf[p] = __nv_bfloat162(__float2bfloat16(v0 - __bfloat162float(h0)),
                                      __float2bfloat16(v1 - __bfloat162float(h1)));
        }
        *(uint4*)(g_Whi + o)     = *(uint4*)&hibuf[0];
        *(uint4*)(g_Whi + o + 8) = *(uint4*)&hibuf[4];
        *(uint4*)(g_Wlo + o)     = *(uint4*)&lobuf[0];
        *(uint4*)(g_Wlo + o + 8) = *(uint4*)&lobuf[4];
    }
}

// ---------------------------------------------------------------------------
// Kernel 3: split X into bf16 hi/lo
// ---------------------------------------------------------------------------
__global__ void split_x_kernel(const float* __restrict__ x) {
    int idx = blockIdx.x * blockDim.x + threadIdx.x;
    float4 v = ((const float4*)x)[idx];
    __nv_bfloat16 h0 = __float2bfloat16(v.x);
    __nv_bfloat16 h1 = __float2bfloat16(v.y);
    __nv_bfloat16 h2 = __float2bfloat16(v.z);
    __nv_bfloat16 h3 = __float2bfloat16(v.w);
    __nv_bfloat16 l0 = __float2bfloat16(v.x - __bfloat162float(h0));
    __nv_bfloat16 l1 = __float2bfloat16(v.y - __bfloat162float(h1));
    __nv_bfloat16 l2 = __float2bfloat16(v.z - __bfloat162float(h2));
    __nv_bfloat16 l3 = __float2bfloat16(v.w - __bfloat162float(h3));
    __nv_bfloat162* Hp = (__nv_bfloat162*)g_Xhi;
    __nv_bfloat162* Lp = (__nv_bfloat162*)g_Xlo;
    Hp[idx * 2 + 0] = __nv_bfloat162(h0, h1);
    Hp[idx * 2 + 1] = __nv_bfloat162(h2, h3);
    Lp[idx * 2 + 0] = __nv_bfloat162(l0, l1);
    Lp[idx * 2 + 1] = __nv_bfloat162(l2, l3);
}

// ---------------------------------------------------------------------------
// Kernel 4: HMMA GEMM. C[1024,4096] = Xsplit @ Wsplit^T + bias
// CTA 128x128, BK=64, SW128 swizzle, 2-stage cp.async, 512 threads.
// 16 warps = 4(M) x 4(N); warp tile 32x32; ~95 regs (no cap).
// ---------------------------------------------------------------------------
#define GBM 128
#define GBN 128
#define GBK 64
#define NKT (KDIM / GBK)            // 64
#define ST_AHI 0
#define ST_ALO 16384
#define ST_BHI 32768
#define ST_BLO 49152
#define STAGE_BYTES 65536
#define SMEM_TOTAL (2 * STAGE_BYTES)   // 128 KB
#define NTHREADS 512

__device__ __forceinline__ void load_stage(uint32_t st, int bm, int bn,
                                           int kt, int tid) {
    const size_t krow = (size_t)kt * 128;     // byte offset within K row
#pragma unroll
    for (int c = tid; c < 1024; c += NTHREADS) {   // 128 rows x 8 16B-chunks
        int row = c >> 3, ch = c & 7;
        uint32_t so = (uint32_t)(row * 128 + ch * 16);
        so ^= (so >> 3) & 0x70;
        const size_t ga = (size_t)(bm + row) * 8192 + krow + ch * 16;
        const size_t gb = (size_t)(bn + row) * 8192 + krow + ch * 16;
        cpasync16(st + ST_AHI + so, (const char*)g_Xhi + ga);
        cpasync16(st + ST_ALO + so, (const char*)g_Xlo + ga);
        cpasync16(st + ST_BHI + so, (const char*)g_Whi + gb);
        cpasync16(st + ST_BLO + so, (const char*)g_Wlo + gb);
    }
}

__global__ __launch_bounds__(NTHREADS, 1)
void gemm_mma_kernel(const float* __restrict__ bias, float* __restrict__ C) {
    extern __shared__ __align__(1024) char smem[];
    const uint32_t sbase = smem_u32(smem);
    const int tid  = threadIdx.x;
    const int wid  = tid >> 5;
    const int lane = tid & 31;
    const int wm = wid & 3;          // 4 M-warps (32 rows each)
    const int wn = wid >> 2;         // 4 N-warps (32 cols each)
    const int bm = blockIdx.y * GBM;
    const int bn = blockIdx.x * GBN;

    const int lrow   = lane & 15;
    const int lchunk = (lane >> 4) * 16;

    // A tiles: rows wm*32 + mt*16 + lrow
    uint32_t a_base[2], a_mask[2];
#pragma unroll
    for (int mt = 0; mt < 2; ++mt) {
        int r = wm * 32 + mt * 16 + lrow;
        a_base[mt] = (uint32_t)(r * 128);
        a_mask[mt] = (uint32_t)((r & 7) << 4);
    }
    // B n16-chunks: rows wn*32 + c*16 + lrow
    uint32_t b_base[2], b_mask[2];
#pragma unroll
    for (int c = 0; c < 2; ++c) {
        int r = wn * 32 + c * 16 + lrow;
        b_base[c] = (uint32_t)(r * 128);
        b_mask[c] = (uint32_t)((r & 7) << 4);
    }

    float acc[2][4][4];
#pragma unroll
    for (int mt = 0; mt < 2; ++mt)
#pragma unroll
        for (int nt = 0; nt < 4; ++nt)
#pragma unroll
            for (int e = 0; e < 4; ++e) acc[mt][nt][e] = 0.f;

    load_stage(sbase, bm, bn, 0, tid);
    asm volatile("cp.async.commit_group;" ::: "memory");

    int buf = 0;
    for (int kt = 0; kt < NKT; ++kt) {
        if (kt + 1 < NKT) {
            load_stage(sbase + (buf ^ 1) * STAGE_BYTES, bm, bn, kt + 1, tid);
            asm volatile("cp.async.commit_group;" ::: "memory");
            asm volatile("cp.async.wait_group 1;" ::: "memory");
        } else {
            asm volatile("cp.async.wait_group 0;" ::: "memory");
        }
        __syncthreads();

        const uint32_t st = sbase + buf * STAGE_BYTES;
#pragma unroll
        for (int ks = 0; ks < 4; ++ks) {
            const uint32_t kb = (uint32_t)(ks * 32);
            uint32_t ah[2][4], al[2][4];
#pragma unroll
            for (int mt = 0; mt < 2; ++mt) {
                uint32_t col = (lchunk + kb) ^ a_mask[mt];
                ldsm4(ah[mt][0], ah[mt][1], ah[mt][2], ah[mt][3],
                      st + ST_AHI + a_base[mt] + col);
                ldsm4(al[mt][0], al[mt][1], al[mt][2], al[mt][3],
                      st + ST_ALO + a_base[mt] + col);
            }
#pragma unroll
            for (int c = 0; c < 2; ++c) {
                uint32_t col = (lchunk + kb) ^ b_mask[c];
                uint32_t bh[4], bl[4];
                ldsm4(bh[0], bh[1], bh[2], bh[3], st + ST_BHI + b_base[c] + col);
                ldsm4(bl[0], bl[1], bl[2], bl[3], st + ST_BLO + b_base[c] + col);
#pragma unroll
                for (int mt = 0; mt < 2; ++mt)
#pragma unroll
                    for (int o = 0; o < 2; ++o) {
                        const int nt = c * 2 + o;
                        mma16816(acc[mt][nt], ah[mt], bh[o], bh[o + 2]);
                        mma16816(acc[mt][nt], ah[mt], bl[o], bl[o + 2]);
                        mma16816(acc[mt][nt], al[mt], bh[o], bh[o + 2]);
                    }
            }
        }
        __syncthreads();
        buf ^= 1;
    }

    // epilogue
    const int gq = lane >> 2, rq = lane & 3;
#pragma unroll
    for (int mt = 0; mt < 2; ++mt) {
        const int r0 = bm + wm * 32 + mt * 16 + gq;
#pragma unroll
        for (int nt = 0; nt < 4; ++nt) {
            const int col = bn + wn * 32 + nt * 8 + rq * 2;
            float2 bv = *(const float2*)&bias[col];
            float2 o0 = make_float2(acc[mt][nt][0] + bv.x, acc[mt][nt][1] + bv.y);
            float2 o1 = make_float2(acc[mt][nt][2] + bv.x, acc[mt][nt][3] + bv.y);
            *(float2*)&C[(size_t)r0 * NDIM + col]       = o0;
            *(float2*)&C[(size_t)(r0 + 8) * NDIM + col] = o1;
        }
    }
}

// ---------------------------------------------------------------------------
extern "C" void kernel_launch(void* const* d_in, const int* in_sizes, int n_in,
                              void* d_out, int out_size) {
    const float* x     = (const float*)d_in[0];
    const float* core0 = (const float*)d_in[1];
    const float* core1 = (const float*)d_in[2];
    const float* core2 = (const float*)d_in[3];
    const float* bias  = (const float*)d_in[4];
    float* out = (float*)d_out;

    build_t01_kernel<<<(256 * 256 * 8) / 256, 256>>>(core0, core1);
    build_w_kernel<<<dim3(4, 256), 256>>>(core2);
    split_x_kernel<<<(MDIM * KDIM / 4) / 256, 256>>>(x);

    cudaFuncSetAttribute(gemm_mma_kernel,
                         cudaFuncAttributeMaxDynamicSharedMemorySize, SMEM_TOTAL);
    gemm_mma_kernel<<<dim3(NDIM / GBN, MDIM / GBM), NTHREADS, SMEM_TOTAL>>>(bias, out);
}

// round 6
// speedup vs baseline: 1.1578x; 1.0220x over previous
#include <cuda_runtime.h>
#include <cuda_bf16.h>
#include <cstdint>

// ===========================================================================
// TrainableMPOLayer: y = X @ W^T + bias, W = dense collapse of 3-core MPO.
//   1) T01 = core0 x core1
//   2) Whi/Wlo bf16 = split(T01 x core2)     [smem-tiled batched GEMM]
//   3) Xhi/Xlo bf16 = split(x)
//   4) Y = Xhi*Whi + Xhi*Wlo + Xlo*Whi + bias  via mma.sync bf16 (HMMA)
//      512 threads, 16 warps (4Mx4N, warp tile 32x32), BK=64, SW128 swizzle,
//      3-stage cp.async pipeline, ONE __syncthreads per K-tile.
// ===========================================================================

#define KDIM 4096
#define MDIM 1024
#define NDIM 4096

__device__ float          g_T01[256 * 256 * 32];        // 8 MB
__device__ __nv_bfloat16  g_Whi[(size_t)4096 * 4096];   // 32 MB
__device__ __nv_bfloat16  g_Wlo[(size_t)4096 * 4096];   // 32 MB
__device__ __nv_bfloat16  g_Xhi[(size_t)1024 * 4096];   // 8 MB
__device__ __nv_bfloat16  g_Xlo[(size_t)1024 * 4096];   // 8 MB

// ---------------------------------------------------------------------------
// helpers
// ---------------------------------------------------------------------------
__device__ __forceinline__ uint32_t smem_u32(const void* p) {
    uint32_t a;
    asm("{ .reg .u64 t; cvta.to.shared.u64 t, %1; cvt.u32.u64 %0, t; }"
        : "=r"(a) : "l"(p));
    return a;
}

__device__ __forceinline__ void cpasync16(uint32_t dst, const void* src) {
    asm volatile("cp.async.cg.shared.global [%0], [%1], 16;"
                 :: "r"(dst), "l"(src) : "memory");
}

__device__ __forceinline__ void ldsm4(uint32_t& r0, uint32_t& r1,
                                      uint32_t& r2, uint32_t& r3, uint32_t a) {
    asm volatile("ldmatrix.sync.aligned.m8n8.x4.shared.b16 {%0,%1,%2,%3}, [%4];"
                 : "=r"(r0), "=r"(r1), "=r"(r2), "=r"(r3) : "r"(a));
}

__device__ __forceinline__ void mma16816(float* d, const uint32_t* a,
                                         uint32_t b0, uint32_t b1) {
    asm volatile(
        "mma.sync.aligned.m16n8k16.row.col.f32.bf16.bf16.f32 "
        "{%0,%1,%2,%3}, {%4,%5,%6,%7}, {%8,%9}, {%0,%1,%2,%3};"
        : "+f"(d[0]), "+f"(d[1]), "+f"(d[2]), "+f"(d[3])
        : "r"(a[0]), "r"(a[1]), "r"(a[2]), "r"(a[3]), "r"(b0), "r"(b1));
}

// ---------------------------------------------------------------------------
// Kernel 1: T01[ii, jj, r2] = sum_r1 core0[i1,j1,r1] * core1[r1,i2,j2,r2]
// ---------------------------------------------------------------------------
__global__ void build_t01_kernel(const float* __restrict__ c0,
                                 const float* __restrict__ c1) {
    int idx = blockIdx.x * blockDim.x + threadIdx.x;   // 0 .. 256*256*8-1
    int r2q = idx & 7;
    int jj  = (idx >> 3) & 255;
    int ii  = idx >> 11;
    int j1 = jj >> 4, j2 = jj & 15;
    int i1 = ii >> 4, i2 = ii & 15;

    const float*  a = c0 + (i1 * 16 + j1) * 32;
    const float4* b = (const float4*)(c1 + i2 * 512 + j2 * 32 + r2q * 4);

    float4 s = make_float4(0.f, 0.f, 0.f, 0.f);
#pragma unroll
    for (int r1 = 0; r1 < 32; ++r1) {
        float  av = a[r1];
        float4 bv = b[(size_t)r1 * 2048];
        s.x += av * bv.x; s.y += av * bv.y; s.z += av * bv.z; s.w += av * bv.w;
    }
    *(float4*)(g_T01 + (size_t)idx * 4) = s;
}

// ---------------------------------------------------------------------------
// Kernel 2: per block: one ii (16 W-rows), 64 jj (1024 W-cols), smem-tiled.
// ---------------------------------------------------------------------------
#define T01T_PITCH 68

__global__ __launch_bounds__(256)
void build_w_kernel(const float* __restrict__ c2) {
    __shared__ __align__(16) float c2s[32 * 256];
    __shared__ __align__(16) float t01t[32 * T01T_PITCH];

    const int tid = threadIdx.x;
    const int ii  = blockIdx.y;
    const int jjb = blockIdx.x * 64;

#pragma unroll
    for (int c = tid; c < 2048; c += 256)
        *(float4*)&c2s[c * 4] = *(const float4*)&c2[c * 4];
#pragma unroll
    for (int c = tid; c < 2048; c += 256) {
        int jj = c >> 5, r2 = c & 31;
        t01t[r2 * T01T_PITCH + jj] = g_T01[((size_t)ii * 256 + jjb + jj) * 32 + r2];
    }
    __syncthreads();

    const int jjg = tid >> 4;
    const int i3  = tid & 15;

    float acc[4][16];
#pragma unroll
    for (int a = 0; a < 4; ++a)
#pragma unroll
        for (int b = 0; b < 16; ++b) acc[a][b] = 0.f;

#pragma unroll
    for (int r2 = 0; r2 < 32; ++r2) {
        float4 tv = *(const float4*)&t01t[r2 * T01T_PITCH + jjg * 4];
        const float* crow = &c2s[r2 * 256 + i3 * 16];
        float4 cv0 = *(const float4*)&crow[0];
        float4 cv1 = *(const float4*)&crow[4];
        float4 cv2 = *(const float4*)&crow[8];
        float4 cv3 = *(const float4*)&crow[12];
        float cva[16] = {cv0.x, cv0.y, cv0.z, cv0.w, cv1.x, cv1.y, cv1.z, cv1.w,
                         cv2.x, cv2.y, cv2.z, cv2.w, cv3.x, cv3.y, cv3.z, cv3.w};
        float tva[4] = {tv.x, tv.y, tv.z, tv.w};
#pragma unroll
        for (int a = 0; a < 4; ++a)
#pragma unroll
            for (int b = 0; b < 16; ++b)
                acc[a][b] += tva[a] * cva[b];
    }

    const size_t rowoff = (size_t)(ii * 16 + i3) * 4096;
#pragma unroll
    for (int a = 0; a < 4; ++a) {
        const size_t o = rowoff + (size_t)(jjb + jjg * 4 + a) * 16;
        __nv_bfloat162 hibuf[8], lobuf[8];
#pragma unroll
        for (int p = 0; p < 8; ++p) {
            float v0 = acc[a][2 * p], v1 = acc[a][2 * p + 1];
            __nv_bfloat16 h0 = __float2bfloat16(v0);
            __nv_bfloat16 h1 = __float2bfloat16(v1);
            hibuf[p] = __nv_bfloat162(h0, h1);
            lobuf[p] = __nv_bfloat162(__float2bfloat16(v0 - __bfloat162float(h0)),
                                      __float2bfloat16(v1 - __bfloat162float(h1)));
        }
        *(uint4*)(g_Whi + o)     = *(uint4*)&hibuf[0];
        *(uint4*)(g_Whi + o + 8) = *(uint4*)&hibuf[4];
        *(uint4*)(g_Wlo + o)     = *(uint4*)&lobuf[0];
        *(uint4*)(g_Wlo + o + 8) = *(uint4*)&lobuf[4];
    }
}

// ---------------------------------------------------------------------------
// Kernel 3: split X into bf16 hi/lo
// ---------------------------------------------------------------------------
__global__ void split_x_kernel(const float* __restrict__ x) {
    int idx = blockIdx.x * blockDim.x + threadIdx.x;
    float4 v = ((const float4*)x)[idx];
    __nv_bfloat16 h0 = __float2bfloat16(v.x);
    __nv_bfloat16 h1 = __float2bfloat16(v.y);
    __nv_bfloat16 h2 = __float2bfloat16(v.z);
    __nv_bfloat16 h3 = __float2bfloat16(v.w);
    __nv_bfloat16 l0 = __float2bfloat16(v.x - __bfloat162float(h0));
    __nv_bfloat16 l1 = __float2bfloat16(v.y - __bfloat162float(h1));
    __nv_bfloat16 l2 = __float2bfloat16(v.z - __bfloat162float(h2));
    __nv_bfloat16 l3 = __float2bfloat16(v.w - __bfloat162float(h3));
    __nv_bfloat162* Hp = (__nv_bfloat162*)g_Xhi;
    __nv_bfloat162* Lp = (__nv_bfloat162*)g_Xlo;
    Hp[idx * 2 + 0] = __nv_bfloat162(h0, h1);
    Hp[idx * 2 + 1] = __nv_bfloat162(h2, h3);
    Lp[idx * 2 + 0] = __nv_bfloat162(l0, l1);
    Lp[idx * 2 + 1] = __nv_bfloat162(l2, l3);
}

// ---------------------------------------------------------------------------
// Kernel 4: HMMA GEMM. C[1024,4096] = Xsplit @ Wsplit^T + bias
// CTA 128x128, BK=64, SW128 swizzle, 3-stage cp.async, 512 threads.
// 16 warps = 4(M) x 4(N); warp tile 32x32. One __syncthreads per K-tile.
// ---------------------------------------------------------------------------
#define GBM 128
#define GBN 128
#define GBK 64
#define NKT (KDIM / GBK)            // 64
#define ST_AHI 0
#define ST_ALO 16384
#define ST_BHI 32768
#define ST_BLO 49152
#define STAGE_BYTES 65536
#define NSTAGE 3
#define SMEM_TOTAL (NSTAGE * STAGE_BYTES)   // 192 KB
#define NTHREADS 512

__device__ __forceinline__ void load_stage(uint32_t st, int bm, int bn,
                                           int kt, int tid) {
    const size_t krow = (size_t)kt * 128;     // byte offset within K row
#pragma unroll
    for (int c = tid; c < 1024; c += NTHREADS) {   // 128 rows x 8 16B-chunks
        int row = c >> 3, ch = c & 7;
        uint32_t so = (uint32_t)(row * 128 + ch * 16);
        so ^= (so >> 3) & 0x70;
        const size_t ga = (size_t)(bm + row) * 8192 + krow + ch * 16;
        const size_t gb = (size_t)(bn + row) * 8192 + krow + ch * 16;
        cpasync16(st + ST_AHI + so, (const char*)g_Xhi + ga);
        cpasync16(st + ST_ALO + so, (const char*)g_Xlo + ga);
        cpasync16(st + ST_BHI + so, (const char*)g_Whi + gb);
        cpasync16(st + ST_BLO + so, (const char*)g_Wlo + gb);
    }
}

__global__ __launch_bounds__(NTHREADS, 1)
void gemm_mma_kernel(const float* __restrict__ bias, float* __restrict__ C) {
    extern __shared__ __align__(1024) char smem[];
    const uint32_t sbase = smem_u32(smem);
    const int tid  = threadIdx.x;
    const int wid  = tid >> 5;
    const int lane = tid & 31;
    const int wm = wid & 3;          // 4 M-warps (32 rows each)
    const int wn = wid >> 2;         // 4 N-warps (32 cols each)
    const int bm = blockIdx.y * GBM;
    const int bn = blockIdx.x * GBN;

    const int lrow   = lane & 15;
    const int lchunk = (lane >> 4) * 16;

    uint32_t a_base[2], a_mask[2];
#pragma unroll
    for (int mt = 0; mt < 2; ++mt) {
        int r = wm * 32 + mt * 16 + lrow;
        a_base[mt] = (uint32_t)(r * 128);
        a_mask[mt] = (uint32_t)((r & 7) << 4);
    }
    uint32_t b_base[2], b_mask[2];
#pragma unroll
    for (int c = 0; c < 2; ++c) {
        int r = wn * 32 + c * 16 + lrow;
        b_base[c] = (uint32_t)(r * 128);
        b_mask[c] = (uint32_t)((r & 7) << 4);
    }

    float acc[2][4][4];
#pragma unroll
    for (int mt = 0; mt < 2; ++mt)
#pragma unroll
        for (int nt = 0; nt < 4; ++nt)
#pragma unroll
            for (int e = 0; e < 4; ++e) acc[mt][nt][e] = 0.f;

    // prologue: stages 0 and 1 in flight
    load_stage(sbase + 0 * STAGE_BYTES, bm, bn, 0, tid);
    asm volatile("cp.async.commit_group;" ::: "memory");
    load_stage(sbase + 1 * STAGE_BYTES, bm, bn, 1, tid);
    asm volatile("cp.async.commit_group;" ::: "memory");

    int slot = 0;
    for (int kt = 0; kt < NKT; ++kt) {
        if (kt + 1 < NKT)
            asm volatile("cp.async.wait_group 1;" ::: "memory");
        else
            asm volatile("cp.async.wait_group 0;" ::: "memory");
        __syncthreads();   // all warps done computing slot (kt-1)%3; tile kt landed

        // prefetch tile kt+2 into the slot freed by tile kt-1
        if (kt + 2 < NKT) {
            int ns = slot + 2; if (ns >= NSTAGE) ns -= NSTAGE;
            load_stage(sbase + ns * STAGE_BYTES, bm, bn, kt + 2, tid);
            asm volatile("cp.async.commit_group;" ::: "memory");
        }

        const uint32_t st = sbase + slot * STAGE_BYTES;
#pragma unroll
        for (int ks = 0; ks < 4; ++ks) {
            const uint32_t kb = (uint32_t)(ks * 32);
            uint32_t ah[2][4], al[2][4];
#pragma unroll
            for (int mt = 0; mt < 2; ++mt) {
                uint32_t col = (lchunk + kb) ^ a_mask[mt];
                ldsm4(ah[mt][0], ah[mt][1], ah[mt][2], ah[mt][3],
                      st + ST_AHI + a_base[mt] + col);
                ldsm4(al[mt][0], al[mt][1], al[mt][2], al[mt][3],
                      st + ST_ALO + a_base[mt] + col);
            }
#pragma unroll
            for (int c = 0; c < 2; ++c) {
                uint32_t col = (lchunk + kb) ^ b_mask[c];
                uint32_t bh[4], bl[4];
                ldsm4(bh[0], bh[1], bh[2], bh[3], st + ST_BHI + b_base[c] + col);
                ldsm4(bl[0], bl[1], bl[2], bl[3], st + ST_BLO + b_base[c] + col);
#pragma unroll
                for (int mt = 0; mt < 2; ++mt)
#pragma unroll
                    for (int o = 0; o < 2; ++o) {
                        const int nt = c * 2 + o;
                        mma16816(acc[mt][nt], ah[mt], bh[o], bh[o + 2]);
                        mma16816(acc[mt][nt], ah[mt], bl[o], bl[o + 2]);
                        mma16816(acc[mt][nt], al[mt], bh[o], bh[o + 2]);
                    }
            }
        }
        ++slot; if (slot >= NSTAGE) slot = 0;
    }

    // epilogue
    const int gq = lane >> 2, rq = lane & 3;
#pragma unroll
    for (int mt = 0; mt < 2; ++mt) {
        const int r0 = bm + wm * 32 + mt * 16 + gq;
#pragma unroll
        for (int nt = 0; nt < 4; ++nt) {
            const int col = bn + wn * 32 + nt * 8 + rq * 2;
            float2 bv = *(const float2*)&bias[col];
            float2 o0 = make_float2(acc[mt][nt][0] + bv.x, acc[mt][nt][1] + bv.y);
            float2 o1 = make_float2(acc[mt][nt][2] + bv.x, acc[mt][nt][3] + bv.y);
            *(float2*)&C[(size_t)r0 * NDIM + col]       = o0;
            *(float2*)&C[(size_t)(r0 + 8) * NDIM + col] = o1;
        }
    }
}

// ---------------------------------------------------------------------------
extern "C" void kernel_launch(void* const* d_in, const int* in_sizes, int n_in,
                              void* d_out, int out_size) {
    const float* x     = (const float*)d_in[0];
    const float* core0 = (const float*)d_in[1];
    const float* core1 = (const float*)d_in[2];
    const float* core2 = (const float*)d_in[3];
    const float* bias  = (const float*)d_in[4];
    float* out = (float*)d_out;

    build_t01_kernel<<<(256 * 256 * 8) / 256, 256>>>(core0, core1);
    build_w_kernel<<<dim3(4, 256), 256>>>(core2);
    split_x_kernel<<<(MDIM * KDIM / 4) / 256, 256>>>(x);

    cudaFuncSetAttribute(gemm_mma_kernel,
                         cudaFuncAttributeMaxDynamicSharedMemorySize, SMEM_TOTAL);
    gemm_mma_kernel<<<dim3(NDIM / GBN, MDIM / GBM), NTHREADS, SMEM_TOTAL>>>(bias, out);
}